// round 2
// baseline (speedup 1.0000x reference)
#include <cuda_runtime.h>

// Problem constants (from reference):
// B=16384, NUM_CARDS=64, NUM_WORDS=50, LEN_EMB=128, LEN_DENSE=128
#define NC 64
#define NW 50
#define D  128
#define EPS 1e-8f

__global__ __launch_bounds__(128, 8)
void imaginarium_kernel(const float* __restrict__ img,   // [B, NC, D]
                        const float* __restrict__ txt,   // [B, NW, D]
                        const float* __restrict__ y,     // [B, NC]
                        const float* __restrict__ W,     // [D, D] row-major (out, in)
                        const float* __restrict__ bias,  // [D]
                        float* __restrict__ out)         // [B, NW]
{
    const int b    = blockIdx.x;
    const int tid  = threadIdx.x;       // 128 threads
    const int lane = tid & 31;
    const int warp = tid >> 5;

    __shared__ float s_x[D];        // selected image row
    __shared__ float s_leader[D];   // Linear output
    __shared__ float s_logit[NW];
    __shared__ float s_red[4];
    __shared__ int   s_idx;

    // ---- 1) argmax over 64 cards (first-index tie-break, like jnp.argmax) ----
    if (warp == 0) {
        float v0 = y[(long)b * NC + lane];
        float v1 = y[(long)b * NC + lane + 32];
        float best; int bi;
        if (v1 > v0) { best = v1; bi = lane + 32; }  // tie -> keep lower index (v0)
        else         { best = v0; bi = lane; }
        #pragma unroll
        for (int off = 16; off; off >>= 1) {
            float ov = __shfl_down_sync(0xffffffffu, best, off);
            int   oi = __shfl_down_sync(0xffffffffu, bi,   off);
            if (ov > best || (ov == best && oi < bi)) { best = ov; bi = oi; }
        }
        if (lane == 0) s_idx = bi;
    }
    __syncthreads();
    const int idx = s_idx;

    // ---- 2) stage selected image row to smem ----
    s_x[tid] = img[((long)b * NC + idx) * D + tid];
    __syncthreads();

    // ---- 3) matvec: leader[e] = sum_d x[d] * W[e,d] + bias[e] ----
    // W row for this thread: 128 floats = 32 float4 (L1/L2-resident across grid)
    const float4* W4 = reinterpret_cast<const float4*>(W + (long)tid * D);
    float acc = 0.f;
    #pragma unroll
    for (int i = 0; i < 32; i++) {
        float4 w = __ldg(&W4[i]);
        acc += w.x * s_x[4*i+0] + w.y * s_x[4*i+1]
             + w.z * s_x[4*i+2] + w.w * s_x[4*i+3];
    }
    const float lv = acc + __ldg(&bias[tid]);
    s_leader[tid] = lv;

    // ---- 4) ||leader|| via block reduction ----
    float sq = lv * lv;
    #pragma unroll
    for (int off = 16; off; off >>= 1)
        sq += __shfl_down_sync(0xffffffffu, sq, off);
    if (lane == 0) s_red[warp] = sq;
    __syncthreads();
    const float na = sqrtf(s_red[0] + s_red[1] + s_red[2] + s_red[3]);

    // ---- 5) cosine similarity per word (float4-vectorized, warp per word) ----
    const float4* txt4 = reinterpret_cast<const float4*>(txt + (long)b * NW * D);
    const float4  l4   = reinterpret_cast<const float4*>(s_leader)[lane];
    for (int w = warp; w < NW; w += 4) {
        float4 t = txt4[w * 32 + lane];
        float dot = l4.x * t.x + l4.y * t.y + l4.z * t.z + l4.w * t.w;
        float nb2 = t.x * t.x + t.y * t.y + t.z * t.z + t.w * t.w;
        #pragma unroll
        for (int off = 16; off; off >>= 1) {
            dot += __shfl_down_sync(0xffffffffu, dot, off);
            nb2 += __shfl_down_sync(0xffffffffu, nb2, off);
        }
        if (lane == 0) {
            float nb = sqrtf(nb2);
            s_logit[w] = dot / fmaxf(na * nb, EPS);
        }
    }
    __syncthreads();

    // ---- 6) softmax over 50 words (single warp) ----
    if (warp == 0) {
        float v0 = s_logit[lane];                                    // lane < 32 < 50
        float v1 = (lane + 32 < NW) ? s_logit[lane + 32] : -1e30f;
        float m = fmaxf(v0, v1);
        #pragma unroll
        for (int off = 16; off; off >>= 1)
            m = fmaxf(m, __shfl_xor_sync(0xffffffffu, m, off));
        float e0 = __expf(v0 - m);
        float e1 = (lane + 32 < NW) ? __expf(v1 - m) : 0.f;
        float s = e0 + e1;
        #pragma unroll
        for (int off = 16; off; off >>= 1)
            s += __shfl_xor_sync(0xffffffffu, s, off);
        const float inv = 1.0f / s;
        float* o = out + (long)b * NW;
        o[lane] = e0 * inv;
        if (lane + 32 < NW) o[lane + 32] = e1 * inv;
    }
}

extern "C" void kernel_launch(void* const* d_in, const int* in_sizes, int n_in,
                              void* d_out, int out_size)
{
    const float* img  = (const float*)d_in[0];   // [B, 64, 128]
    const float* txt  = (const float*)d_in[1];   // [B, 50, 128]
    const float* yy   = (const float*)d_in[2];   // [B, 64]
    const float* W    = (const float*)d_in[3];   // [128, 128]
    const float* bias = (const float*)d_in[4];   // [128]
    float* out = (float*)d_out;                  // [B, 50]

    const int B = in_sizes[2] / NC;
    imaginarium_kernel<<<B, 128>>>(img, txt, yy, W, bias, out);
}